// round 13
// baseline (speedup 1.0000x reference)
#include <cuda_runtime.h>
#include <cuda_bf16.h>
#include <math_constants.h>

#define HIDDEN 1024
#define WPB    6      // words per block -> grid 1000 (R8-proven residency)
#define CAP    768    // score window rows (3 KB smem); re-anchors if exceeded

// Fully fused, one kernel, one launch. Each 256-thread block owns WPB
// consecutive words whose spans tile a contiguous row range (~13 rows).
//  Phase 0: warp-ballot dtype sniff (int32 vs int64 indices) + batch idx loads.
//  Phase 1: 8 warps score the block's whole row range in parallel (one warp
//           per row, 8 float4 loads/lane -> high MLP) into smem.
//  Phase 2: R8-style depth-1-pipelined word loop; scores come from smem
//           (29-cyc LDS, no global score dependency), rows are L1-warm from
//           phase 1. Softmax shifted by the first score (seed weight 1);
//           length-1 spans are a pure copy. Bias skipped (shift-invariant).
// The score window re-anchors if a span ever exceeds CAP rows (never in
// practice; correctness guard only).
__global__ void __launch_bounds__(256) fused_kernel(
        const float* __restrict__ hs,
        const void*  __restrict__ starts_raw,
        const void*  __restrict__ ends_raw,
        const float* __restrict__ w_attn,
        float*       __restrict__ out,
        int n_words, int n_sub) {
    __shared__ float sc[CAP];
    __shared__ int   sh_is64;

    int t    = threadIdx.x;
    int warp = t >> 5;
    int lane = t & 31;
    int wbase = blockIdx.x * WPB;
    if (wbase >= n_words) return;
    int nw = min(WPB, n_words - wbase);

    // Phase 0a: dtype sniff. int64-LE values (<2^31) have zero odd int32
    // words; 32 genuine sorted int32 starts can't all be zero there.
    if (warp == 0) {
        const int* pr = (const int*)starts_raw;
        int nchk = n_words < 64 ? (n_words >> 1) : 32;
        int zero = (lane >= nchk) || (pr[2 * lane + 1] == 0);
        unsigned b = __ballot_sync(0xFFFFFFFFu, zero);
        if (lane == 0) sh_is64 = (b == 0xFFFFFFFFu);
    }
    __syncthreads();
    bool is64 = (sh_is64 != 0);

    // Phase 0b: batch index loads (uniform broadcast).
    int s0[WPB], s1[WPB];
#pragma unroll
    for (int k = 0; k < WPB; k++) {
        int w = min(wbase + k, n_words - 1);
        int a, b;
        if (is64) {
            a = (int)((const long long*)starts_raw)[w];
            b = (int)((const long long*)ends_raw)[w];
        } else {
            a = ((const int*)starts_raw)[w];
            b = ((const int*)ends_raw)[w];
        }
        a = max(0, min(a, n_sub - 1));
        b = max(a, min(b, n_sub - 1));
        s0[k] = a;
        s1[k] = b;
    }
    int row_hi = s1[nw - 1];

    const float4* hs4 = reinterpret_cast<const float4*>(hs);
    const float4* wv  = reinterpret_cast<const float4*>(w_attn);

    // Phase 1: score window build (one warp per row; rows are contiguous).
    int win_lo = s0[0];
    {
        int nr = min(row_hi, win_lo + CAP - 1) - win_lo + 1;
        for (int r = warp; r < nr; r += 8) {
            const float4* row = hs4 + (size_t)(win_lo + r) * (HIDDEN / 4);
            float a = 0.0f;
#pragma unroll
            for (int i = 0; i < HIDDEN / 128; i++) {
                float4 x = row[lane + i * 32];
                float4 c = wv[lane + i * 32];
                a += x.x * c.x + x.y * c.y + x.z * c.z + x.w * c.w;
            }
#pragma unroll
            for (int o = 16; o > 0; o >>= 1)
                a += __shfl_xor_sync(0xFFFFFFFFu, a, o);
            if (lane == 0) sc[r] = a;
        }
    }
    __syncthreads();

    // Phase 2: depth-1 pipelined word loop.
    float4 acc = hs4[(size_t)s0[0] * (HIDDEN / 4) + t];

#pragma unroll
    for (int k = 0; k < WPB; k++) {
        if (k >= nw) break;

        // issue next word's seed load before this word's tail
        int ns0 = 0, ns1 = 0;
        float4 nacc;
        bool have_next = (k + 1 < nw);
        if (have_next) {
            ns0  = s0[k + 1];
            ns1  = s1[k + 1];
            nacc = hs4[(size_t)ns0 * (HIDDEN / 4) + t];
        }

        if (s1[k] > s0[k]) {
            // correctness guard: re-anchor window if seed fell outside (uniform)
            if (s0[k] >= win_lo + CAP) {
                __syncthreads();
                win_lo = s0[k];
                int nr = min(row_hi, win_lo + CAP - 1) - win_lo + 1;
                for (int r = warp; r < nr; r += 8) {
                    const float4* row = hs4 + (size_t)(win_lo + r) * (HIDDEN / 4);
                    float a = 0.0f;
#pragma unroll
                    for (int i = 0; i < HIDDEN / 128; i++) {
                        float4 x = row[lane + i * 32];
                        float4 c = wv[lane + i * 32];
                        a += x.x * c.x + x.y * c.y + x.z * c.z + x.w * c.w;
                    }
#pragma unroll
                    for (int o = 16; o > 0; o >>= 1)
                        a += __shfl_xor_sync(0xFFFFFFFFu, a, o);
                    if (lane == 0) sc[r] = a;
                }
                __syncthreads();
            }
            float ref = sc[s0[k] - win_lo];
            float Z = 1.0f;
            for (int s = s0[k] + 1; s <= s1[k]; s++) {
                if (s >= win_lo + CAP) {   // correctness guard (uniform)
                    __syncthreads();
                    win_lo = s;
                    int nr = min(row_hi, win_lo + CAP - 1) - win_lo + 1;
                    for (int r = warp; r < nr; r += 8) {
                        const float4* row = hs4 + (size_t)(win_lo + r) * (HIDDEN / 4);
                        float a = 0.0f;
#pragma unroll
                        for (int i = 0; i < HIDDEN / 128; i++) {
                            float4 x = row[lane + i * 32];
                            float4 c = wv[lane + i * 32];
                            a += x.x * c.x + x.y * c.y + x.z * c.z + x.w * c.w;
                        }
#pragma unroll
                        for (int o = 16; o > 0; o >>= 1)
                            a += __shfl_xor_sync(0xFFFFFFFFu, a, o);
                        if (lane == 0) sc[r] = a;
                    }
                    __syncthreads();
                }
                float p = __expf(sc[s - win_lo] - ref);
                Z += p;
                float4 v = hs4[(size_t)s * (HIDDEN / 4) + t];
                acc.x += p * v.x;
                acc.y += p * v.y;
                acc.z += p * v.z;
                acc.w += p * v.w;
            }
            float inv = 1.0f / Z;
            acc.x *= inv; acc.y *= inv; acc.z *= inv; acc.w *= inv;
        }

        reinterpret_cast<float4*>(out)[(size_t)(wbase + k) * (HIDDEN / 4) + t] = acc;

        if (have_next) acc = nacc;
    }
}

extern "C" void kernel_launch(void* const* d_in, const int* in_sizes, int n_in,
                              void* d_out, int out_size) {
    const float* hs     = (const float*)d_in[0];   // [n_sub, 1024]
    const void*  starts = d_in[1];                 // [n_words] int32 or int64
    const void*  ends   = d_in[2];                 // [n_words]
    const float* w_attn = (const float*)d_in[3];   // [1024, 1]
    float*       out    = (float*)d_out;           // [n_words, 1024]

    int n_sub   = in_sizes[0] / HIDDEN;
    int n_words = in_sizes[1];

    fused_kernel<<<(n_words + WPB - 1) / WPB, 256>>>(
        hs, starts, ends, w_attn, out, n_words, n_sub);
}

// round 17
// speedup vs baseline: 1.5560x; 1.5560x over previous
#include <cuda_runtime.h>
#include <cuda_bf16.h>
#include <math_constants.h>

#define HIDDEN 1024
#define MAX_SUBWORDS 8192
#define WPB    6     // words per pool block (grid ~1000, R8-proven)

__device__ float g_scores[MAX_SUBWORDS];

// Kernel 1 (primary): scores[s] = dot(hidden[s], w), one warp per row.
// Bias skipped (softmax shift-invariant). Triggers programmatic launch
// completion so the pool kernel's prologue overlaps our tail.
__global__ void __launch_bounds__(256) scores_kernel(
        const float* __restrict__ hs,
        const float* __restrict__ w_attn,
        int n_sub) {
    int warp = (blockIdx.x * blockDim.x + threadIdx.x) >> 5;
    int lane = threadIdx.x & 31;
    if (warp < n_sub) {
        const float4* row = reinterpret_cast<const float4*>(hs + (size_t)warp * HIDDEN);
        const float4* wv  = reinterpret_cast<const float4*>(w_attn);

        float acc = 0.0f;
#pragma unroll
        for (int i = 0; i < HIDDEN / 128; i++) {
            float4 a = row[lane + i * 32];
            float4 c = wv[lane + i * 32];
            acc += a.x * c.x + a.y * c.y + a.z * c.z + a.w * c.w;
        }
#pragma unroll
        for (int o = 16; o > 0; o >>= 1)
            acc += __shfl_xor_sync(0xFFFFFFFFu, acc, o);

        if (lane == 0) g_scores[warp] = acc;
    }
    cudaTriggerProgrammaticLaunchCompletion();
}

// Kernel 2 (secondary, PDL): R8 word-chunked streaming pool. The prologue
// (dtype sniff, index loads, first seed-row load) is independent of scores
// and runs BEFORE cudaGridDependencySynchronize(), overlapping the scores
// kernel's execution. Depth-1 pipeline: word w+1's indices + seed row are
// issued before word w's softmax tail. Softmax shifted by the first score
// (seed enters at weight exp(0)=1); length-1 spans are a pure copy.
__global__ void __launch_bounds__(256) pool_kernel(
        const float* __restrict__ hs,
        const void*  __restrict__ starts_raw,
        const void*  __restrict__ ends_raw,
        float*       __restrict__ out,
        int n_words, int n_sub) {
    int t     = threadIdx.x;                 // float4 column
    int lane  = t & 31;
    int wbase = blockIdx.x * WPB;
    int wend  = min(wbase + WPB, n_words);
    if (wbase >= wend) { cudaGridDependencySynchronize(); return; }

    // dtype sniff, per-warp ballot (no smem/sync; L1-broadcast loads):
    // int64-LE values (<2^31) have zero odd int32 words; 32 genuine sorted
    // int32 starts over [0,8192) can't all be zero there.
    const int* pr = (const int*)starts_raw;
    int nchk = n_words < 64 ? (n_words >> 1) : 32;
    int zero = (lane >= nchk) || (pr[2 * lane + 1] == 0);
    bool is64 = (__ballot_sync(0xFFFFFFFFu, zero) == 0xFFFFFFFFu);

    const float4* hs4 = reinterpret_cast<const float4*>(hs);

    // prologue (score-independent): first word's indices + seed row
    int s0, s1;
    if (is64) {
        s0 = (int)((const long long*)starts_raw)[wbase];
        s1 = (int)((const long long*)ends_raw)[wbase];
    } else {
        s0 = ((const int*)starts_raw)[wbase];
        s1 = ((const int*)ends_raw)[wbase];
    }
    s0 = max(0, min(s0, n_sub - 1));
    s1 = max(s0, min(s1, n_sub - 1));
    float4 acc = hs4[(size_t)s0 * (HIDDEN / 4) + t];

    // wait for scores_kernel to complete (seed load stays in flight)
    cudaGridDependencySynchronize();

    for (int w = wbase; w < wend; w++) {
        // issue next word's index + seed loads before this word's tail
        int ns0 = 0, ns1 = 0;
        float4 nacc;
        bool have_next = (w + 1 < wend);
        if (have_next) {
            if (is64) {
                ns0 = (int)((const long long*)starts_raw)[w + 1];
                ns1 = (int)((const long long*)ends_raw)[w + 1];
            } else {
                ns0 = ((const int*)starts_raw)[w + 1];
                ns1 = ((const int*)ends_raw)[w + 1];
            }
            ns0 = max(0, min(ns0, n_sub - 1));
            ns1 = max(ns0, min(ns1, n_sub - 1));
            nacc = hs4[(size_t)ns0 * (HIDDEN / 4) + t];
        }

        if (s1 > s0) {
            float ref = g_scores[s0];        // broadcast, L1-resident
            float Z = 1.0f;
            for (int s = s0 + 1; s <= s1; s++) {
                float p = __expf(g_scores[s] - ref);
                Z += p;
                float4 v = hs4[(size_t)s * (HIDDEN / 4) + t];
                acc.x += p * v.x;
                acc.y += p * v.y;
                acc.z += p * v.z;
                acc.w += p * v.w;
            }
            float inv = 1.0f / Z;
            acc.x *= inv; acc.y *= inv; acc.z *= inv; acc.w *= inv;
        }

        reinterpret_cast<float4*>(out)[(size_t)w * (HIDDEN / 4) + t] = acc;

        if (have_next) { s0 = ns0; s1 = ns1; acc = nacc; }
    }
}

extern "C" void kernel_launch(void* const* d_in, const int* in_sizes, int n_in,
                              void* d_out, int out_size) {
    const float* hs     = (const float*)d_in[0];   // [n_sub, 1024]
    const void*  starts = d_in[1];                 // [n_words] int32 or int64
    const void*  ends   = d_in[2];                 // [n_words]
    const float* w_attn = (const float*)d_in[3];   // [1024, 1]
    float*       out    = (float*)d_out;           // [n_words, 1024]

    int n_sub   = in_sizes[0] / HIDDEN;
    int n_words = in_sizes[1];

    // Primary: scores (one warp per row; 8 rows per 256-thr block).
    scores_kernel<<<(n_sub + 7) / 8, 256>>>(hs, w_attn, n_sub);

    // Secondary: pool, launched with programmatic dependent launch so its
    // score-independent prologue overlaps the scores kernel.
    cudaLaunchConfig_t cfg = {};
    cfg.gridDim  = dim3((n_words + WPB - 1) / WPB, 1, 1);
    cfg.blockDim = dim3(256, 1, 1);
    cfg.dynamicSmemBytes = 0;
    cfg.stream = 0;   // legacy default stream (same as <<<>>>), capture-safe
    cudaLaunchAttribute attrs[1];
    attrs[0].id = cudaLaunchAttributeProgrammaticStreamSerialization;
    attrs[0].val.programmaticStreamSerializationAllowed = 1;
    cfg.attrs = attrs;
    cfg.numAttrs = 1;
    cudaLaunchKernelEx(&cfg, pool_kernel, hs, (const void*)starts,
                       (const void*)ends, out, n_words, n_sub);
}